// round 14
// baseline (speedup 1.0000x reference)
#include <cuda_runtime.h>
#include <cuda_fp16.h>
#include <cstdint>

#define DM 1024
#define QSCALE 0.18033688f   // log2(e)/8, folded into q at projection

// Scratch (device globals: allocation-free per harness rules)
__device__ __half g_xh[(size_t)3 * 8192 * 1024];   // fp16 query/key_/value
__device__ __half g_whq[1024 * 1024];              // per-head Wq as [n=h*64+dk][k=m]
__device__ __half g_whk[1024 * 1024];
__device__ __half g_whv[1024 * 1024];
__device__ __half g_woh[1024 * 1024];              // Wo [n][k] fp16
__device__ __half g_qh[(size_t)8192 * 1024];
__device__ __half g_kh[(size_t)8192 * 1024];
__device__ __half g_vh[(size_t)8192 * 1024];
__device__ __half g_eh[(size_t)64 * 2048 * 2048];  // E = exp2(scores') fp16 (512 MiB)
__device__ float  g_part[64 * 16 * 2048];
__device__ __half g_vt[(size_t)64 * 64 * 2048];    // V'^T fp16 [z][dk][s], 1/Z folded
__device__ __half g_ctxh[(size_t)8192 * 1024];

// ---------------------------------------------------------------------------
// helpers
// ---------------------------------------------------------------------------
__device__ __forceinline__ unsigned packh2(float lo, float hi) {
    unsigned r; asm("cvt.rn.f16x2.f32 %0, %1, %2;" : "=r"(r) : "f"(hi), "f"(lo)); return r;
}
__device__ __forceinline__ void mma_f16(float* c, const unsigned* a, const unsigned* b) {
    asm volatile("mma.sync.aligned.m16n8k16.row.col.f32.f16.f16.f32 "
        "{%0,%1,%2,%3},{%4,%5,%6,%7},{%8,%9},{%0,%1,%2,%3};"
        : "+f"(c[0]), "+f"(c[1]), "+f"(c[2]), "+f"(c[3])
        : "r"(a[0]), "r"(a[1]), "r"(a[2]), "r"(a[3]), "r"(b[0]), "r"(b[1]));
}
__device__ __forceinline__ void cp16(void* dst, const void* src) {
    unsigned d = (unsigned)__cvta_generic_to_shared(dst);
    asm volatile("cp.async.ca.shared.global [%0], [%1], 16;\n" :: "r"(d), "l"(src));
}
#define LDMX4(r0, r1, r2, r3, addr) \
    asm volatile("ldmatrix.sync.aligned.m8n8.x4.shared.b16 {%0,%1,%2,%3}, [%4];" \
        : "=r"(r0), "=r"(r1), "=r"(r2), "=r"(r3) : "r"(addr))
__device__ __forceinline__ uint32_t s2u(const void* p) {
    return (uint32_t)__cvta_generic_to_shared(p);
}

// ---------------------------------------------------------------------------
// Conversions
// ---------------------------------------------------------------------------
__global__ __launch_bounds__(256) void cvt_x(const float* __restrict__ q,
                                             const float* __restrict__ k,
                                             const float* __restrict__ v)
{
    const int z = blockIdx.z;
    const float* src = (z == 0) ? q : (z == 1) ? k : v;
    __half* dst = g_xh + (size_t)z * 8192 * 1024;
    size_t i = ((size_t)blockIdx.x * 256 + threadIdx.x) << 2;
    float4 val = *(const float4*)&src[i];
    *(uint2*)&dst[i] = make_uint2(packh2(val.x, val.y), packh2(val.z, val.w));
}

__global__ __launch_bounds__(256) void cvt_w(const float* __restrict__ Wq,
                                             const float* __restrict__ Wk,
                                             const float* __restrict__ Wv)
{
    __shared__ float T[64][65];
    const int z = blockIdx.z;
    const float* W = (z == 0) ? Wq : (z == 1) ? Wk : Wv;
    __half* out = (z == 0) ? g_whq : (z == 1) ? g_whk : g_whv;
    const int h = blockIdx.y, k0 = blockIdx.x << 6;
    const int tid = threadIdx.x;
    #pragma unroll
    for (int i = 0; i < 4; i++) {
        int idx = tid + (i << 8);
        int kk = idx >> 4, j = (idx & 15) << 2;
        float4 v = *(const float4*)&W[(h << 16) + ((k0 + kk) << 6) + j];
        T[kk][j] = v.x; T[kk][j + 1] = v.y; T[kk][j + 2] = v.z; T[kk][j + 3] = v.w;
    }
    __syncthreads();
    #pragma unroll
    for (int i = 0; i < 4; i++) {
        int idx = tid + (i << 8);
        int dk = idx >> 4, kk = (idx & 15) << 2;
        uint2 u = make_uint2(packh2(T[kk][dk], T[kk + 1][dk]),
                             packh2(T[kk + 2][dk], T[kk + 3][dk]));
        *(uint2*)&out[(size_t)((h << 6) + dk) * 1024 + k0 + kk] = u;
    }
}

__global__ __launch_bounds__(256) void cvt_wo(const float* __restrict__ Wo)
{
    size_t i = ((size_t)blockIdx.x * 256 + threadIdx.x) << 2;
    float4 val = *(const float4*)&Wo[i];
    *(uint2*)&g_woh[i] = make_uint2(packh2(val.x, val.y), packh2(val.z, val.w));
}

// ---------------------------------------------------------------------------
// Generic fp16 GEMM body: C[128 x 128] tile, A[m][k], B[n][k], K=1024, BK=64,
// cp.async double-buffered (validated R8 config), ldmatrix fragment loads.
// 8 warps, warp tile 64x32.
// ---------------------------------------------------------------------------
#define PSTRIDE 72   // halves per smem row (64 + 8 pad); rows 144B apart

struct GemmAcc { float a[4][4][4]; };

__device__ __forceinline__ void hgemm_core(const __half* __restrict__ Ap,
                                           const __half* __restrict__ Bp,
                                           __half* sm, GemmAcc& g,
                                           int row0, int col0)
{
    const int tid = threadIdx.x, lane = tid & 31, warp = tid >> 5;
    const int wm = warp >> 2, wn = warp & 3;
    const int STG = 2 * 128 * PSTRIDE;   // halves per stage (A + B)

    #pragma unroll
    for (int i = 0; i < 4; i++)
        #pragma unroll
        for (int j = 0; j < 4; j++)
            #pragma unroll
            for (int k = 0; k < 4; k++) g.a[i][j][k] = 0.f;

    // per-thread ldmatrix address components (bytes)
    const uint32_t arow_off = (uint32_t)(((lane & 15) * PSTRIDE + ((lane >> 4) << 3)) << 1);
    const uint32_t brow_off = (uint32_t)(((((lane & 16) >> 1) + (lane & 7)) * PSTRIDE + (lane & 8)) << 1);

    auto load_stage = [&](int st, int k0) {
        __half* A = sm + st * STG;
        __half* B = A + 128 * PSTRIDE;
        #pragma unroll
        for (int i = 0; i < 4; i++) {
            int idx = tid + (i << 8);
            int r = idx >> 3, w = (idx & 7) << 3;
            cp16(A + r * PSTRIDE + w, Ap + (size_t)(row0 + r) * 1024 + k0 + w);
        }
        #pragma unroll
        for (int i = 0; i < 4; i++) {
            int idx = tid + (i << 8);
            int n = idx >> 3, w = (idx & 7) << 3;
            cp16(B + n * PSTRIDE + w, Bp + (size_t)(col0 + n) * 1024 + k0 + w);
        }
        asm volatile("cp.async.commit_group;\n");
    };

    load_stage(0, 0);
    for (int it = 0; it < 16; it++) {
        const int st = it & 1;
        if (it + 1 < 16) {
            load_stage(st ^ 1, (it + 1) << 6);
            asm volatile("cp.async.wait_group 1;\n");
        } else {
            asm volatile("cp.async.wait_group 0;\n");
        }
        __syncthreads();
        const uint32_t Au = s2u(sm + st * STG);
        const uint32_t Bu = Au + (uint32_t)(128 * PSTRIDE * 2);
        #pragma unroll
        for (int ks = 0; ks < 4; ks++) {
            const int kb0 = ks << 4;
            unsigned a[4][4], bf[4][2];
            #pragma unroll
            for (int fm = 0; fm < 4; fm++) {
                uint32_t addr = Au + arow_off +
                    (uint32_t)(((((wm << 6) + (fm << 4)) * PSTRIDE + kb0)) << 1);
                LDMX4(a[fm][0], a[fm][1], a[fm][2], a[fm][3], addr);
            }
            #pragma unroll
            for (int p = 0; p < 2; p++) {
                uint32_t addr = Bu + brow_off +
                    (uint32_t)(((((wn << 5) + (p << 4)) * PSTRIDE + kb0)) << 1);
                LDMX4(bf[2 * p][0], bf[2 * p][1], bf[2 * p + 1][0], bf[2 * p + 1][1], addr);
            }
            #pragma unroll
            for (int fm = 0; fm < 4; fm++)
                #pragma unroll
                for (int fn = 0; fn < 4; fn++)
                    mma_f16(g.a[fm][fn], a[fm], bf[fn]);
        }
        __syncthreads();
    }
}

#define PROJ_SMEM (2 * 2 * 128 * PSTRIDE * 2)   // bytes: 2 stages x (A+B)

// Projections: q/k/v = Xh @ Wh^T + bias, output fp16.
// For zc==0 (q) the whole result (incl. bias) is scaled by log2(e)/8 so the
// scores kernel can use bare exp2f.
__global__ __launch_bounds__(256, 2) void proj_hgemm(
    const float* __restrict__ bq, const float* __restrict__ bk, const float* __restrict__ bv)
{
    extern __shared__ __align__(16) __half psm[];
    const int zc = blockIdx.z;
    const __half* X  = g_xh + (size_t)zc * 8192 * 1024;
    const __half* Wh = (zc == 0) ? g_whq : (zc == 1) ? g_whk : g_whv;
    const float* bias = (zc == 0) ? bq : (zc == 1) ? bk : bv;
    __half* out = (zc == 0) ? g_qh : (zc == 1) ? g_kh : g_vh;
    const float sc = (zc == 0) ? QSCALE : 1.0f;

    const int row0 = blockIdx.y << 7, col0 = blockIdx.x << 7;
    GemmAcc g;
    hgemm_core(X, Wh, psm, g, row0, col0);

    const int lane = threadIdx.x & 31, warp = threadIdx.x >> 5;
    const int wm = warp >> 2, wn = warp & 3;
    const int rb = lane >> 2, c2 = (lane & 3) << 1;
    #pragma unroll
    for (int fn = 0; fn < 4; fn++) {
        int c = col0 + (wn << 5) + (fn << 3) + c2;
        float b0 = bias[c], b1 = bias[c + 1];
        #pragma unroll
        for (int fm = 0; fm < 4; fm++) {
            int r = row0 + (wm << 6) + (fm << 4) + rb;
            *(unsigned*)&out[(size_t)r * 1024 + c] =
                packh2((g.a[fm][fn][0] + b0) * sc, (g.a[fm][fn][1] + b1) * sc);
            *(unsigned*)&out[(size_t)(r + 8) * 1024 + c] =
                packh2((g.a[fm][fn][2] + b0) * sc, (g.a[fm][fn][3] + b1) * sc);
        }
    }
}

// Output projection: out = ctx @ Wo^T + bo, fp32 output.
__global__ __launch_bounds__(256, 2) void out_hgemm(const float* __restrict__ bo,
                                                    float* __restrict__ out)
{
    extern __shared__ __align__(16) __half psm[];
    const int row0 = blockIdx.y << 7, col0 = blockIdx.x << 7;
    GemmAcc g;
    hgemm_core(g_ctxh, g_woh, psm, g, row0, col0);

    const int lane = threadIdx.x & 31, warp = threadIdx.x >> 5;
    const int wm = warp >> 2, wn = warp & 3;
    const int rb = lane >> 2, c2 = (lane & 3) << 1;
    #pragma unroll
    for (int fn = 0; fn < 4; fn++) {
        int c = col0 + (wn << 5) + (fn << 3) + c2;
        float b0 = bo[c], b1 = bo[c + 1];
        #pragma unroll
        for (int fm = 0; fm < 4; fm++) {
            int r = row0 + (wm << 6) + (fm << 4) + rb;
            *(float2*)&out[(size_t)r * 1024 + c] =
                make_float2(g.a[fm][fn][0] + b0, g.a[fm][fn][1] + b1);
            *(float2*)&out[(size_t)(r + 8) * 1024 + c] =
                make_float2(g.a[fm][fn][2] + b0, g.a[fm][fn][3] + b1);
        }
    }
}

// ---------------------------------------------------------------------------
// Scores pass (once): 128q x 128s tile per (b,h), fp16 QK^T (K=64),
// E = exp2(q'.k) -> fp16 to g_eh (staged uint4 stores), column partials.
// (q pre-scaled by log2(e)/8 at projection.)
// ---------------------------------------------------------------------------
#define SSTRIDE 72
__global__ __launch_bounds__(256) void scores_hmma()
{
    __shared__ __align__(16) __half qk[2 * 128 * SSTRIDE];
    __shared__ float red[16][128];
    __half* Qs = qk;
    __half* Ks = qk + 128 * SSTRIDE;
    __half* Estage = qk;   // reused after mma: [128][136]

    const int tid = threadIdx.x, lane = tid & 31, warp = tid >> 5;
    const int wm = warp >> 2, wn = warp & 3;
    const int z = blockIdx.z, b = z >> 4, h = z & 15;
    const int q0 = blockIdx.y << 7, s0 = blockIdx.x << 7;
    const __half* qh = g_qh + (size_t)b * 2048 * 1024 + h * 64;
    const __half* kh = g_kh + (size_t)b * 2048 * 1024 + h * 64;

    #pragma unroll
    for (int i = 0; i < 4; i++) {
        int idx = tid + (i << 8);
        int r = idx >> 3, w = (idx & 7) << 3;
        *(uint4*)&Qs[r * SSTRIDE + w] = *(const uint4*)&qh[(size_t)(q0 + r) * 1024 + w];
        *(uint4*)&Ks[r * SSTRIDE + w] = *(const uint4*)&kh[(size_t)(s0 + r) * 1024 + w];
    }
    __syncthreads();

    float acc[4][4][4];
    #pragma unroll
    for (int i = 0; i < 4; i++)
        #pragma unroll
        for (int j = 0; j < 4; j++)
            #pragma unroll
            for (int k = 0; k < 4; k++) acc[i][j][k] = 0.f;

    const uint32_t Qu = s2u(Qs), Ku = s2u(Ks);
    const uint32_t arow_off = (uint32_t)(((lane & 15) * SSTRIDE + ((lane >> 4) << 3)) << 1);
    const uint32_t brow_off = (uint32_t)(((((lane & 16) >> 1) + (lane & 7)) * SSTRIDE + (lane & 8)) << 1);
    const int rb = lane >> 2, c2 = (lane & 3) << 1;

    #pragma unroll
    for (int ks = 0; ks < 4; ks++) {
        const int kb0 = ks << 4;
        unsigned a[4][4], bf[4][2];
        #pragma unroll
        for (int fm = 0; fm < 4; fm++) {
            uint32_t addr = Qu + arow_off +
                (uint32_t)((((wm << 6) + (fm << 4)) * SSTRIDE + kb0) << 1);
            LDMX4(a[fm][0], a[fm][1], a[fm][2], a[fm][3], addr);
        }
        #pragma unroll
        for (int p = 0; p < 2; p++) {
            uint32_t addr = Ku + brow_off +
                (uint32_t)((((wn << 5) + (p << 4)) * SSTRIDE + kb0) << 1);
            LDMX4(bf[2 * p][0], bf[2 * p][1], bf[2 * p + 1][0], bf[2 * p + 1][1], addr);
        }
        #pragma unroll
        for (int fm = 0; fm < 4; fm++)
            #pragma unroll
            for (int fn = 0; fn < 4; fn++)
                mma_f16(acc[fm][fn], a[fm], bf[fn]);
    }
    __syncthreads();

    float colacc[8];
    #pragma unroll
    for (int i = 0; i < 8; i++) colacc[i] = 0.f;
    #pragma unroll
    for (int fm = 0; fm < 4; fm++) {
        int m0 = (wm << 6) + (fm << 4) + rb;
        #pragma unroll
        for (int fn = 0; fn < 4; fn++) {
            int n = (wn << 5) + (fn << 3) + c2;
            float e0 = exp2f(acc[fm][fn][0]);
            float e1 = exp2f(acc[fm][fn][1]);
            float e2 = exp2f(acc[fm][fn][2]);
            float e3 = exp2f(acc[fm][fn][3]);
            colacc[2 * fn]     += e0 + e2;
            colacc[2 * fn + 1] += e1 + e3;
            *(unsigned*)&Estage[m0 * 136 + n]       = packh2(e0, e1);
            *(unsigned*)&Estage[(m0 + 8) * 136 + n] = packh2(e2, e3);
        }
    }
    __syncthreads();

    __half* ez = g_eh + (size_t)z * 2048 * 2048;
    #pragma unroll
    for (int i = 0; i < 8; i++) {
        int idx = tid + (i << 8);
        int q = idx >> 4, w = idx & 15;
        *(uint4*)(ez + (size_t)(q0 + q) * 2048 + s0 + (w << 3)) =
            *(uint4*)&Estage[q * 136 + (w << 3)];
    }

    const int rg = (wm << 3) + rb;
    #pragma unroll
    for (int fn = 0; fn < 4; fn++) {
        int cc = (wn << 5) + (fn << 3) + c2;
        red[rg][cc]     = colacc[2 * fn];
        red[rg][cc + 1] = colacc[2 * fn + 1];
    }
    __syncthreads();
    if (tid < 128) {
        float s = 0.f;
        #pragma unroll
        for (int t = 0; t < 16; t++) s += red[t][tid];
        g_part[((size_t)z * 16 + blockIdx.y) * 2048 + s0 + tid] = s;
    }
}

// ---------------------------------------------------------------------------
// V' = V * rz -> fp16 transposed: g_vt[z][dk][s].
// rz computed inline from the 16 per-qtile partials (recip kernel fused).
// ---------------------------------------------------------------------------
__global__ __launch_bounds__(256) void v2h_fold()
{
    __shared__ float T[64][68];
    __shared__ float rzs[64];
    const int tid = threadIdx.x;
    const int z = blockIdx.y, b = z >> 4, h = z & 15;
    const int s0 = blockIdx.x << 6;
    const __half* vh = g_vh + (size_t)b * 2048 * 1024 + h * 64;
    #pragma unroll
    for (int i = 0; i < 4; i++) {
        int idx = tid + (i << 8);
        int s = idx >> 4, j = (idx & 15) << 2;
        const __half* p = vh + (size_t)(s0 + s) * 1024 + j;
        T[s][j]     = __half2float(p[0]);
        T[s][j + 1] = __half2float(p[1]);
        T[s][j + 2] = __half2float(p[2]);
        T[s][j + 3] = __half2float(p[3]);
    }
    if (tid < 64) {
        float s = 0.f;
        #pragma unroll
        for (int t = 0; t < 16; t++)
            s += g_part[((size_t)z * 16 + t) * 2048 + s0 + tid];
        rzs[tid] = 1.0f / s;
    }
    __syncthreads();
    __half* outp = g_vt + (size_t)z * 64 * 2048;
    #pragma unroll
    for (int i = 0; i < 4; i++) {
        int idx = tid + (i << 8);
        int dk = idx >> 4, sj = (idx & 15) << 2;
        uint2 u;
        u.x = packh2(T[sj][dk] * rzs[sj],         T[sj + 1][dk] * rzs[sj + 1]);
        u.y = packh2(T[sj + 2][dk] * rzs[sj + 2], T[sj + 3][dk] * rzs[sj + 3]);
        *(uint2*)(outp + dk * 2048 + s0 + sj) = u;
    }
}

// ---------------------------------------------------------------------------
// ctx = Eh @ V'^T per (b,h): [2048 x 64] = [2048 x 2048] x [2048 x 64].
// OCCUPANCY EXPERIMENT: block 128q x 64dk; 8 warps, each 16q x 64dk;
// 55 KB smem, 3 CTAs/SM. fp16 mma, fp32 accum, cp.async double-buffered,
// ldmatrix loads; fp16 out.
// ---------------------------------------------------------------------------
#define CSTRIDE 72
__global__ __launch_bounds__(256, 3) void ctx_hgemm()
{
    extern __shared__ __align__(16) __half hsm[];
    const int STG = (128 + 64) * CSTRIDE;   // halves per stage (E 128 rows + V 64 rows)

    const int tid = threadIdx.x, lane = tid & 31, warp = tid >> 5;
    const int z = blockIdx.y, b = z >> 4, h = z & 15;
    const int q0 = blockIdx.x << 7;
    const __half* ez = g_eh + (size_t)z * 2048 * 2048;
    const __half* vt = g_vt + (size_t)z * 64 * 2048;

    float acc[8][4];
    #pragma unroll
    for (int i = 0; i < 8; i++)
        #pragma unroll
        for (int j = 0; j < 4; j++) acc[i][j] = 0.f;

    const uint32_t arow_off = (uint32_t)(((lane & 15) * CSTRIDE + ((lane >> 4) << 3)) << 1);
    const uint32_t brow_off = (uint32_t)(((((lane & 16) >> 1) + (lane & 7)) * CSTRIDE + (lane & 8)) << 1);

    auto load_stage = [&](int st, int s0) {
        __half* E = hsm + st * STG;
        __half* V = E + 128 * CSTRIDE;
        #pragma unroll
        for (int i = 0; i < 4; i++) {
            int idx = tid + (i << 8);
            int q = idx >> 3, w = idx & 7;
            cp16(E + q * CSTRIDE + (w << 3), ez + (size_t)(q0 + q) * 2048 + s0 + (w << 3));
        }
        #pragma unroll
        for (int i = 0; i < 2; i++) {
            int idx = tid + (i << 8);
            int dk = idx >> 3, w = idx & 7;
            cp16(V + dk * CSTRIDE + (w << 3), vt + dk * 2048 + s0 + (w << 3));
        }
        asm volatile("cp.async.commit_group;\n");
    };

    load_stage(0, 0);
    for (int it = 0; it < 32; it++) {
        const int st = it & 1;
        if (it + 1 < 32) {
            load_stage(st ^ 1, (it + 1) << 6);
            asm volatile("cp.async.wait_group 1;\n");
        } else {
            asm volatile("cp.async.wait_group 0;\n");
        }
        __syncthreads();
        const uint32_t Eu = s2u(hsm + st * STG);
        const uint32_t Vu = Eu + (uint32_t)(128 * CSTRIDE * 2);
        const int m0 = warp << 4;
        #pragma unroll
        for (int kk = 0; kk < 4; kk++) {
            const int kb0 = kk << 4;
            unsigned a[4];
            LDMX4(a[0], a[1], a[2], a[3],
                  Eu + arow_off + (uint32_t)((m0 * CSTRIDE + kb0) << 1));
            unsigned bf[8][2];
            #pragma unroll
            for (int p = 0; p < 4; p++) {
                LDMX4(bf[2 * p][0], bf[2 * p][1], bf[2 * p + 1][0], bf[2 * p + 1][1],
                      Vu + brow_off + (uint32_t)(((p << 4) * CSTRIDE + kb0) << 1));
            }
            #pragma unroll
            for (int fb = 0; fb < 8; fb++)
                mma_f16(acc[fb], a, bf[fb]);
        }
        __syncthreads();
    }

    __half* outp = g_ctxh + ((size_t)b * 2048 + q0) * 1024 + h * 64;
    const int c2 = (lane & 3) << 1;
    const int q = (warp << 4) + (lane >> 2);
    #pragma unroll
    for (int fb = 0; fb < 8; fb++) {
        int dk = (fb << 3) + c2;
        *(unsigned*)&outp[(size_t)q * 1024 + dk]       = packh2(acc[fb][0], acc[fb][1]);
        *(unsigned*)&outp[(size_t)(q + 8) * 1024 + dk] = packh2(acc[fb][2], acc[fb][3]);
    }
}

extern "C" void kernel_launch(void* const* d_in, const int* in_sizes, int n_in,
                              void* d_out, int out_size)
{
    const float* query = (const float*)d_in[0];
    const float* key_  = (const float*)d_in[1];
    const float* value = (const float*)d_in[2];
    const float* Wq    = (const float*)d_in[3];
    const float* bq    = (const float*)d_in[4];
    const float* Wk    = (const float*)d_in[5];
    const float* bk    = (const float*)d_in[6];
    const float* Wv    = (const float*)d_in[7];
    const float* bv    = (const float*)d_in[8];
    const float* Wo    = (const float*)d_in[9];
    const float* bo    = (const float*)d_in[10];
    float* out = (float*)d_out;

    const int ctx_smem = 2 * (128 + 64) * CSTRIDE * 2;   // 55296 bytes
    cudaFuncSetAttribute(proj_hgemm, cudaFuncAttributeMaxDynamicSharedMemorySize, PROJ_SMEM);
    cudaFuncSetAttribute(out_hgemm,  cudaFuncAttributeMaxDynamicSharedMemorySize, PROJ_SMEM);
    cudaFuncSetAttribute(ctx_hgemm,  cudaFuncAttributeMaxDynamicSharedMemorySize, ctx_smem);

    cvt_x<<<dim3(8192, 1, 3), 256>>>(query, key_, value);
    cvt_w<<<dim3(16, 16, 3), 256>>>(Wq, Wk, Wv);
    cvt_wo<<<1024, 256>>>(Wo);
    proj_hgemm<<<dim3(8, 64, 3), 256, PROJ_SMEM>>>(bq, bk, bv);
    scores_hmma<<<dim3(16, 16, 64), 256>>>();
    v2h_fold<<<dim3(32, 64), 256>>>();
    ctx_hgemm<<<dim3(16, 64), 256, ctx_smem>>>();
    out_hgemm<<<dim3(8, 64), 256, PROJ_SMEM>>>(bo, out);
}

// round 15
// speedup vs baseline: 1.0076x; 1.0076x over previous
#include <cuda_runtime.h>
#include <cuda_fp16.h>
#include <cstdint>

#define DM 1024
#define QSCALE 0.18033688f   // log2(e)/8, folded into q at projection

// Scratch (device globals: allocation-free per harness rules)
__device__ __half g_xh[(size_t)3 * 8192 * 1024];   // fp16 query/key_/value
__device__ __half g_whq[1024 * 1024];              // per-head Wq as [n=h*64+dk][k=m]
__device__ __half g_whk[1024 * 1024];
__device__ __half g_whv[1024 * 1024];
__device__ __half g_woh[1024 * 1024];              // Wo [n][k] fp16
__device__ __half g_qh[(size_t)8192 * 1024];
__device__ __half g_kh[(size_t)8192 * 1024];
__device__ __half g_vh[(size_t)8192 * 1024];
__device__ __half g_eh[(size_t)64 * 2048 * 2048];  // E = exp2(scores') fp16 (512 MiB)
__device__ float  g_part[64 * 16 * 2048];
__device__ __half g_vt[(size_t)64 * 64 * 2048];    // V'^T fp16 [z][dk][s], 1/Z folded
__device__ __half g_ctxh[(size_t)8192 * 1024];

// ---------------------------------------------------------------------------
// helpers
// ---------------------------------------------------------------------------
__device__ __forceinline__ unsigned packh2(float lo, float hi) {
    unsigned r; asm("cvt.rn.f16x2.f32 %0, %1, %2;" : "=r"(r) : "f"(hi), "f"(lo)); return r;
}
__device__ __forceinline__ void mma_f16(float* c, const unsigned* a, const unsigned* b) {
    asm volatile("mma.sync.aligned.m16n8k16.row.col.f32.f16.f16.f32 "
        "{%0,%1,%2,%3},{%4,%5,%6,%7},{%8,%9},{%0,%1,%2,%3};"
        : "+f"(c[0]), "+f"(c[1]), "+f"(c[2]), "+f"(c[3])
        : "r"(a[0]), "r"(a[1]), "r"(a[2]), "r"(a[3]), "r"(b[0]), "r"(b[1]));
}
__device__ __forceinline__ void cp16(void* dst, const void* src) {
    unsigned d = (unsigned)__cvta_generic_to_shared(dst);
    asm volatile("cp.async.ca.shared.global [%0], [%1], 16;\n" :: "r"(d), "l"(src));
}
#define LDMX4(r0, r1, r2, r3, addr) \
    asm volatile("ldmatrix.sync.aligned.m8n8.x4.shared.b16 {%0,%1,%2,%3}, [%4];" \
        : "=r"(r0), "=r"(r1), "=r"(r2), "=r"(r3) : "r"(addr))
__device__ __forceinline__ uint32_t s2u(const void* p) {
    return (uint32_t)__cvta_generic_to_shared(p);
}

// ---------------------------------------------------------------------------
// Conversions
// ---------------------------------------------------------------------------
__global__ __launch_bounds__(256) void cvt_x(const float* __restrict__ q,
                                             const float* __restrict__ k,
                                             const float* __restrict__ v)
{
    const int z = blockIdx.z;
    const float* src = (z == 0) ? q : (z == 1) ? k : v;
    __half* dst = g_xh + (size_t)z * 8192 * 1024;
    size_t i = ((size_t)blockIdx.x * 256 + threadIdx.x) << 2;
    float4 val = *(const float4*)&src[i];
    *(uint2*)&dst[i] = make_uint2(packh2(val.x, val.y), packh2(val.z, val.w));
}

__global__ __launch_bounds__(256) void cvt_w(const float* __restrict__ Wq,
                                             const float* __restrict__ Wk,
                                             const float* __restrict__ Wv)
{
    __shared__ float T[64][65];
    const int z = blockIdx.z;
    const float* W = (z == 0) ? Wq : (z == 1) ? Wk : Wv;
    __half* out = (z == 0) ? g_whq : (z == 1) ? g_whk : g_whv;
    const int h = blockIdx.y, k0 = blockIdx.x << 6;
    const int tid = threadIdx.x;
    #pragma unroll
    for (int i = 0; i < 4; i++) {
        int idx = tid + (i << 8);
        int kk = idx >> 4, j = (idx & 15) << 2;
        float4 v = *(const float4*)&W[(h << 16) + ((k0 + kk) << 6) + j];
        T[kk][j] = v.x; T[kk][j + 1] = v.y; T[kk][j + 2] = v.z; T[kk][j + 3] = v.w;
    }
    __syncthreads();
    #pragma unroll
    for (int i = 0; i < 4; i++) {
        int idx = tid + (i << 8);
        int dk = idx >> 4, kk = (idx & 15) << 2;
        uint2 u = make_uint2(packh2(T[kk][dk], T[kk + 1][dk]),
                             packh2(T[kk + 2][dk], T[kk + 3][dk]));
        *(uint2*)&out[(size_t)((h << 6) + dk) * 1024 + k0 + kk] = u;
    }
}

__global__ __launch_bounds__(256) void cvt_wo(const float* __restrict__ Wo)
{
    size_t i = ((size_t)blockIdx.x * 256 + threadIdx.x) << 2;
    float4 val = *(const float4*)&Wo[i];
    *(uint2*)&g_woh[i] = make_uint2(packh2(val.x, val.y), packh2(val.z, val.w));
}

// ---------------------------------------------------------------------------
// Generic fp16 GEMM body: C[128 x 128] tile, A[m][k], B[n][k], K=1024, BK=64,
// cp.async double-buffered (validated R8 config), ldmatrix fragment loads.
// 8 warps, warp tile 64x32.
// ---------------------------------------------------------------------------
#define PSTRIDE 72   // halves per smem row (64 + 8 pad); rows 144B apart

struct GemmAcc { float a[4][4][4]; };

__device__ __forceinline__ void hgemm_core(const __half* __restrict__ Ap,
                                           const __half* __restrict__ Bp,
                                           __half* sm, GemmAcc& g,
                                           int row0, int col0)
{
    const int tid = threadIdx.x, lane = tid & 31, warp = tid >> 5;
    const int wm = warp >> 2, wn = warp & 3;
    const int STG = 2 * 128 * PSTRIDE;   // halves per stage (A + B)

    #pragma unroll
    for (int i = 0; i < 4; i++)
        #pragma unroll
        for (int j = 0; j < 4; j++)
            #pragma unroll
            for (int k = 0; k < 4; k++) g.a[i][j][k] = 0.f;

    // per-thread ldmatrix address components (bytes)
    const uint32_t arow_off = (uint32_t)(((lane & 15) * PSTRIDE + ((lane >> 4) << 3)) << 1);
    const uint32_t brow_off = (uint32_t)(((((lane & 16) >> 1) + (lane & 7)) * PSTRIDE + (lane & 8)) << 1);

    auto load_stage = [&](int st, int k0) {
        __half* A = sm + st * STG;
        __half* B = A + 128 * PSTRIDE;
        #pragma unroll
        for (int i = 0; i < 4; i++) {
            int idx = tid + (i << 8);
            int r = idx >> 3, w = (idx & 7) << 3;
            cp16(A + r * PSTRIDE + w, Ap + (size_t)(row0 + r) * 1024 + k0 + w);
        }
        #pragma unroll
        for (int i = 0; i < 4; i++) {
            int idx = tid + (i << 8);
            int n = idx >> 3, w = (idx & 7) << 3;
            cp16(B + n * PSTRIDE + w, Bp + (size_t)(col0 + n) * 1024 + k0 + w);
        }
        asm volatile("cp.async.commit_group;\n");
    };

    load_stage(0, 0);
    for (int it = 0; it < 16; it++) {
        const int st = it & 1;
        if (it + 1 < 16) {
            load_stage(st ^ 1, (it + 1) << 6);
            asm volatile("cp.async.wait_group 1;\n");
        } else {
            asm volatile("cp.async.wait_group 0;\n");
        }
        __syncthreads();
        const uint32_t Au = s2u(sm + st * STG);
        const uint32_t Bu = Au + (uint32_t)(128 * PSTRIDE * 2);
        #pragma unroll
        for (int ks = 0; ks < 4; ks++) {
            const int kb0 = ks << 4;
            unsigned a[4][4], bf[4][2];
            #pragma unroll
            for (int fm = 0; fm < 4; fm++) {
                uint32_t addr = Au + arow_off +
                    (uint32_t)(((((wm << 6) + (fm << 4)) * PSTRIDE + kb0)) << 1);
                LDMX4(a[fm][0], a[fm][1], a[fm][2], a[fm][3], addr);
            }
            #pragma unroll
            for (int p = 0; p < 2; p++) {
                uint32_t addr = Bu + brow_off +
                    (uint32_t)(((((wn << 5) + (p << 4)) * PSTRIDE + kb0)) << 1);
                LDMX4(bf[2 * p][0], bf[2 * p][1], bf[2 * p + 1][0], bf[2 * p + 1][1], addr);
            }
            #pragma unroll
            for (int fm = 0; fm < 4; fm++)
                #pragma unroll
                for (int fn = 0; fn < 4; fn++)
                    mma_f16(g.a[fm][fn], a[fm], bf[fn]);
        }
        __syncthreads();
    }
}

#define PROJ_SMEM (2 * 2 * 128 * PSTRIDE * 2)   // bytes: 2 stages x (A+B)

// Projections: q/k/v = Xh @ Wh^T + bias, output fp16.
// For zc==0 (q) the whole result (incl. bias) is scaled by log2(e)/8 so the
// scores kernel can use bare exp2f.
__global__ __launch_bounds__(256, 2) void proj_hgemm(
    const float* __restrict__ bq, const float* __restrict__ bk, const float* __restrict__ bv)
{
    extern __shared__ __align__(16) __half psm[];
    const int zc = blockIdx.z;
    const __half* X  = g_xh + (size_t)zc * 8192 * 1024;
    const __half* Wh = (zc == 0) ? g_whq : (zc == 1) ? g_whk : g_whv;
    const float* bias = (zc == 0) ? bq : (zc == 1) ? bk : bv;
    __half* out = (zc == 0) ? g_qh : (zc == 1) ? g_kh : g_vh;
    const float sc = (zc == 0) ? QSCALE : 1.0f;

    const int row0 = blockIdx.y << 7, col0 = blockIdx.x << 7;
    GemmAcc g;
    hgemm_core(X, Wh, psm, g, row0, col0);

    const int lane = threadIdx.x & 31, warp = threadIdx.x >> 5;
    const int wm = warp >> 2, wn = warp & 3;
    const int rb = lane >> 2, c2 = (lane & 3) << 1;
    #pragma unroll
    for (int fn = 0; fn < 4; fn++) {
        int c = col0 + (wn << 5) + (fn << 3) + c2;
        float b0 = bias[c], b1 = bias[c + 1];
        #pragma unroll
        for (int fm = 0; fm < 4; fm++) {
            int r = row0 + (wm << 6) + (fm << 4) + rb;
            *(unsigned*)&out[(size_t)r * 1024 + c] =
                packh2((g.a[fm][fn][0] + b0) * sc, (g.a[fm][fn][1] + b1) * sc);
            *(unsigned*)&out[(size_t)(r + 8) * 1024 + c] =
                packh2((g.a[fm][fn][2] + b0) * sc, (g.a[fm][fn][3] + b1) * sc);
        }
    }
}

// Output projection: out = ctx @ Wo^T + bo, fp32 output.
__global__ __launch_bounds__(256, 2) void out_hgemm(const float* __restrict__ bo,
                                                    float* __restrict__ out)
{
    extern __shared__ __align__(16) __half psm[];
    const int row0 = blockIdx.y << 7, col0 = blockIdx.x << 7;
    GemmAcc g;
    hgemm_core(g_ctxh, g_woh, psm, g, row0, col0);

    const int lane = threadIdx.x & 31, warp = threadIdx.x >> 5;
    const int wm = warp >> 2, wn = warp & 3;
    const int rb = lane >> 2, c2 = (lane & 3) << 1;
    #pragma unroll
    for (int fn = 0; fn < 4; fn++) {
        int c = col0 + (wn << 5) + (fn << 3) + c2;
        float b0 = bo[c], b1 = bo[c + 1];
        #pragma unroll
        for (int fm = 0; fm < 4; fm++) {
            int r = row0 + (wm << 6) + (fm << 4) + rb;
            *(float2*)&out[(size_t)r * 1024 + c] =
                make_float2(g.a[fm][fn][0] + b0, g.a[fm][fn][1] + b1);
            *(float2*)&out[(size_t)(r + 8) * 1024 + c] =
                make_float2(g.a[fm][fn][2] + b0, g.a[fm][fn][3] + b1);
        }
    }
}

// ---------------------------------------------------------------------------
// Scores pass (once): 128q x 128s tile per (b,h), fp16 QK^T (K=64),
// E = exp2(q'.k) -> fp16 to g_eh (staged uint4 stores), column partials.
// (q pre-scaled by log2(e)/8 at projection.)
// ---------------------------------------------------------------------------
#define SSTRIDE 72
__global__ __launch_bounds__(256) void scores_hmma()
{
    __shared__ __align__(16) __half qk[2 * 128 * SSTRIDE];
    __shared__ float red[16][128];
    __half* Qs = qk;
    __half* Ks = qk + 128 * SSTRIDE;
    __half* Estage = qk;   // reused after mma: [128][136]

    const int tid = threadIdx.x, lane = tid & 31, warp = tid >> 5;
    const int wm = warp >> 2, wn = warp & 3;
    const int z = blockIdx.z, b = z >> 4, h = z & 15;
    const int q0 = blockIdx.y << 7, s0 = blockIdx.x << 7;
    const __half* qh = g_qh + (size_t)b * 2048 * 1024 + h * 64;
    const __half* kh = g_kh + (size_t)b * 2048 * 1024 + h * 64;

    #pragma unroll
    for (int i = 0; i < 4; i++) {
        int idx = tid + (i << 8);
        int r = idx >> 3, w = (idx & 7) << 3;
        *(uint4*)&Qs[r * SSTRIDE + w] = *(const uint4*)&qh[(size_t)(q0 + r) * 1024 + w];
        *(uint4*)&Ks[r * SSTRIDE + w] = *(const uint4*)&kh[(size_t)(s0 + r) * 1024 + w];
    }
    __syncthreads();

    float acc[4][4][4];
    #pragma unroll
    for (int i = 0; i < 4; i++)
        #pragma unroll
        for (int j = 0; j < 4; j++)
            #pragma unroll
            for (int k = 0; k < 4; k++) acc[i][j][k] = 0.f;

    const uint32_t Qu = s2u(Qs), Ku = s2u(Ks);
    const uint32_t arow_off = (uint32_t)(((lane & 15) * SSTRIDE + ((lane >> 4) << 3)) << 1);
    const uint32_t brow_off = (uint32_t)(((((lane & 16) >> 1) + (lane & 7)) * SSTRIDE + (lane & 8)) << 1);
    const int rb = lane >> 2, c2 = (lane & 3) << 1;

    #pragma unroll
    for (int ks = 0; ks < 4; ks++) {
        const int kb0 = ks << 4;
        unsigned a[4][4], bf[4][2];
        #pragma unroll
        for (int fm = 0; fm < 4; fm++) {
            uint32_t addr = Qu + arow_off +
                (uint32_t)((((wm << 6) + (fm << 4)) * SSTRIDE + kb0) << 1);
            LDMX4(a[fm][0], a[fm][1], a[fm][2], a[fm][3], addr);
        }
        #pragma unroll
        for (int p = 0; p < 2; p++) {
            uint32_t addr = Ku + brow_off +
                (uint32_t)((((wn << 5) + (p << 4)) * SSTRIDE + kb0) << 1);
            LDMX4(bf[2 * p][0], bf[2 * p][1], bf[2 * p + 1][0], bf[2 * p + 1][1], addr);
        }
        #pragma unroll
        for (int fm = 0; fm < 4; fm++)
            #pragma unroll
            for (int fn = 0; fn < 4; fn++)
                mma_f16(acc[fm][fn], a[fm], bf[fn]);
    }
    __syncthreads();

    float colacc[8];
    #pragma unroll
    for (int i = 0; i < 8; i++) colacc[i] = 0.f;
    #pragma unroll
    for (int fm = 0; fm < 4; fm++) {
        int m0 = (wm << 6) + (fm << 4) + rb;
        #pragma unroll
        for (int fn = 0; fn < 4; fn++) {
            int n = (wn << 5) + (fn << 3) + c2;
            float e0 = exp2f(acc[fm][fn][0]);
            float e1 = exp2f(acc[fm][fn][1]);
            float e2 = exp2f(acc[fm][fn][2]);
            float e3 = exp2f(acc[fm][fn][3]);
            colacc[2 * fn]     += e0 + e2;
            colacc[2 * fn + 1] += e1 + e3;
            *(unsigned*)&Estage[m0 * 136 + n]       = packh2(e0, e1);
            *(unsigned*)&Estage[(m0 + 8) * 136 + n] = packh2(e2, e3);
        }
    }
    __syncthreads();

    __half* ez = g_eh + (size_t)z * 2048 * 2048;
    #pragma unroll
    for (int i = 0; i < 8; i++) {
        int idx = tid + (i << 8);
        int q = idx >> 4, w = idx & 15;
        *(uint4*)(ez + (size_t)(q0 + q) * 2048 + s0 + (w << 3)) =
            *(uint4*)&Estage[q * 136 + (w << 3)];
    }

    const int rg = (wm << 3) + rb;
    #pragma unroll
    for (int fn = 0; fn < 4; fn++) {
        int cc = (wn << 5) + (fn << 3) + c2;
        red[rg][cc]     = colacc[2 * fn];
        red[rg][cc + 1] = colacc[2 * fn + 1];
    }
    __syncthreads();
    if (tid < 128) {
        float s = 0.f;
        #pragma unroll
        for (int t = 0; t < 16; t++) s += red[t][tid];
        g_part[((size_t)z * 16 + blockIdx.y) * 2048 + s0 + tid] = s;
    }
}

// ---------------------------------------------------------------------------
// V' = V * rz -> fp16 transposed: g_vt[z][dk][s].
// rz computed inline from the 16 per-qtile partials (recip kernel fused).
// ---------------------------------------------------------------------------
__global__ __launch_bounds__(256) void v2h_fold()
{
    __shared__ float T[64][68];
    __shared__ float rzs[64];
    const int tid = threadIdx.x;
    const int z = blockIdx.y, b = z >> 4, h = z & 15;
    const int s0 = blockIdx.x << 6;
    const __half* vh = g_vh + (size_t)b * 2048 * 1024 + h * 64;
    #pragma unroll
    for (int i = 0; i < 4; i++) {
        int idx = tid + (i << 8);
        int s = idx >> 4, j = (idx & 15) << 2;
        const __half* p = vh + (size_t)(s0 + s) * 1024 + j;
        T[s][j]     = __half2float(p[0]);
        T[s][j + 1] = __half2float(p[1]);
        T[s][j + 2] = __half2float(p[2]);
        T[s][j + 3] = __half2float(p[3]);
    }
    if (tid < 64) {
        float s = 0.f;
        #pragma unroll
        for (int t = 0; t < 16; t++)
            s += g_part[((size_t)z * 16 + t) * 2048 + s0 + tid];
        rzs[tid] = 1.0f / s;
    }
    __syncthreads();
    __half* outp = g_vt + (size_t)z * 64 * 2048;
    #pragma unroll
    for (int i = 0; i < 4; i++) {
        int idx = tid + (i << 8);
        int dk = idx >> 4, sj = (idx & 15) << 2;
        uint2 u;
        u.x = packh2(T[sj][dk] * rzs[sj],         T[sj + 1][dk] * rzs[sj + 1]);
        u.y = packh2(T[sj + 2][dk] * rzs[sj + 2], T[sj + 3][dk] * rzs[sj + 3]);
        *(uint2*)(outp + dk * 2048 + s0 + sj) = u;
    }
}

// ---------------------------------------------------------------------------
// ctx = Eh @ V'^T per (b,h): [2048 x 64] = [2048 x 2048] x [2048 x 64].
// Block 256q x 64dk; 8 warps, each 32q x 64dk (validated R8 config:
// B frags serve 2x the HMMA, 2 CTAs/SM). fp16 mma, fp32 accum,
// cp.async double-buffered, ldmatrix loads; fp16 out.
// ---------------------------------------------------------------------------
#define CSTRIDE 72
__global__ __launch_bounds__(256, 2) void ctx_hgemm()
{
    extern __shared__ __align__(16) __half hsm[];
    const int STG = (256 + 64) * CSTRIDE;   // halves per stage (E 256 rows + V 64 rows)

    const int tid = threadIdx.x, lane = tid & 31, warp = tid >> 5;
    const int z = blockIdx.y, b = z >> 4, h = z & 15;
    const int q0 = blockIdx.x << 8;
    const __half* ez = g_eh + (size_t)z * 2048 * 2048;
    const __half* vt = g_vt + (size_t)z * 64 * 2048;

    float acc[2][8][4];
    #pragma unroll
    for (int f = 0; f < 2; f++)
        #pragma unroll
        for (int i = 0; i < 8; i++)
            #pragma unroll
            for (int j = 0; j < 4; j++) acc[f][i][j] = 0.f;

    const uint32_t arow_off = (uint32_t)(((lane & 15) * CSTRIDE + ((lane >> 4) << 3)) << 1);
    const uint32_t brow_off = (uint32_t)(((((lane & 16) >> 1) + (lane & 7)) * CSTRIDE + (lane & 8)) << 1);

    auto load_stage = [&](int st, int s0) {
        __half* E = hsm + st * STG;
        __half* V = E + 256 * CSTRIDE;
        #pragma unroll
        for (int i = 0; i < 8; i++) {
            int idx = tid + (i << 8);
            int q = idx >> 3, w = idx & 7;
            cp16(E + q * CSTRIDE + (w << 3), ez + (size_t)(q0 + q) * 2048 + s0 + (w << 3));
        }
        #pragma unroll
        for (int i = 0; i < 2; i++) {
            int idx = tid + (i << 8);
            int dk = idx >> 3, w = idx & 7;
            cp16(V + dk * CSTRIDE + (w << 3), vt + dk * 2048 + s0 + (w << 3));
        }
        asm volatile("cp.async.commit_group;\n");
    };

    load_stage(0, 0);
    for (int it = 0; it < 32; it++) {
        const int st = it & 1;
        if (it + 1 < 32) {
            load_stage(st ^ 1, (it + 1) << 6);
            asm volatile("cp.async.wait_group 1;\n");
        } else {
            asm volatile("cp.async.wait_group 0;\n");
        }
        __syncthreads();
        const uint32_t Eu = s2u(hsm + st * STG);
        const uint32_t Vu = Eu + (uint32_t)(256 * CSTRIDE * 2);
        const int m0 = warp << 5;
        #pragma unroll
        for (int kk = 0; kk < 4; kk++) {
            const int kb0 = kk << 4;
            unsigned a[2][4];
            #pragma unroll
            for (int fm = 0; fm < 2; fm++)
                LDMX4(a[fm][0], a[fm][1], a[fm][2], a[fm][3],
                      Eu + arow_off + (uint32_t)(((m0 + (fm << 4)) * CSTRIDE + kb0) << 1));
            unsigned bf[8][2];
            #pragma unroll
            for (int p = 0; p < 4; p++) {
                LDMX4(bf[2 * p][0], bf[2 * p][1], bf[2 * p + 1][0], bf[2 * p + 1][1],
                      Vu + brow_off + (uint32_t)(((p << 4) * CSTRIDE + kb0) << 1));
            }
            #pragma unroll
            for (int fm = 0; fm < 2; fm++)
                #pragma unroll
                for (int fb = 0; fb < 8; fb++)
                    mma_f16(acc[fm][fb], a[fm], bf[fb]);
        }
        __syncthreads();
    }

    __half* outp = g_ctxh + ((size_t)b * 2048 + q0) * 1024 + h * 64;
    const int c2 = (lane & 3) << 1;
    #pragma unroll
    for (int fm = 0; fm < 2; fm++) {
        const int q = (warp << 5) + (fm << 4) + (lane >> 2);
        #pragma unroll
        for (int fb = 0; fb < 8; fb++) {
            int dk = (fb << 3) + c2;
            *(unsigned*)&outp[(size_t)q * 1024 + dk]       = packh2(acc[fm][fb][0], acc[fm][fb][1]);
            *(unsigned*)&outp[(size_t)(q + 8) * 1024 + dk] = packh2(acc[fm][fb][2], acc[fm][fb][3]);
        }
    }
}

extern "C" void kernel_launch(void* const* d_in, const int* in_sizes, int n_in,
                              void* d_out, int out_size)
{
    const float* query = (const float*)d_in[0];
    const float* key_  = (const float*)d_in[1];
    const float* value = (const float*)d_in[2];
    const float* Wq    = (const float*)d_in[3];
    const float* bq    = (const float*)d_in[4];
    const float* Wk    = (const float*)d_in[5];
    const float* bk    = (const float*)d_in[6];
    const float* Wv    = (const float*)d_in[7];
    const float* bv    = (const float*)d_in[8];
    const float* Wo    = (const float*)d_in[9];
    const float* bo    = (const float*)d_in[10];
    float* out = (float*)d_out;

    const int ctx_smem = 2 * (256 + 64) * CSTRIDE * 2;   // 92160 bytes
    cudaFuncSetAttribute(proj_hgemm, cudaFuncAttributeMaxDynamicSharedMemorySize, PROJ_SMEM);
    cudaFuncSetAttribute(out_hgemm,  cudaFuncAttributeMaxDynamicSharedMemorySize, PROJ_SMEM);
    cudaFuncSetAttribute(ctx_hgemm,  cudaFuncAttributeMaxDynamicSharedMemorySize, ctx_smem);

    cvt_x<<<dim3(8192, 1, 3), 256>>>(query, key_, value);
    cvt_w<<<dim3(16, 16, 3), 256>>>(Wq, Wk, Wv);
    cvt_wo<<<1024, 256>>>(Wo);
    proj_hgemm<<<dim3(8, 64, 3), 256, PROJ_SMEM>>>(bq, bk, bv);
    scores_hmma<<<dim3(16, 16, 64), 256>>>();
    v2h_fold<<<dim3(32, 64), 256>>>();
    ctx_hgemm<<<dim3(8, 64), 256, ctx_smem>>>();
    out_hgemm<<<dim3(8, 64), 256, PROJ_SMEM>>>(bo, out);
}

// round 17
// speedup vs baseline: 1.1138x; 1.1054x over previous
#include <cuda_runtime.h>
#include <cuda_fp16.h>
#include <cstdint>

#define DM 1024
#define QSCALE 0.18033688f   // log2(e)/8, folded into q at projection

// Scratch (device globals: allocation-free per harness rules)
__device__ __half g_xh[(size_t)3 * 8192 * 1024];   // fp16 query/key_/value
__device__ __half g_whq[1024 * 1024];              // per-head Wq as [n=h*64+dk][k=m]
__device__ __half g_whk[1024 * 1024];
__device__ __half g_whv[1024 * 1024];
__device__ __half g_woh[1024 * 1024];              // Wo [n][k] fp16
__device__ __half g_qh[(size_t)8192 * 1024];
__device__ __half g_kh[(size_t)8192 * 1024];
__device__ __half g_vh[(size_t)8192 * 1024];
__device__ __half g_eh[(size_t)64 * 2048 * 2048];  // E = exp2(scores') fp16 (512 MiB)
__device__ float  g_part[64 * 16 * 2048];
__device__ __half g_vt[(size_t)64 * 64 * 2048];    // V'^T fp16 [z][dk][s], 1/Z folded
__device__ __half g_ctxh[(size_t)8192 * 1024];

// ---------------------------------------------------------------------------
// helpers
// ---------------------------------------------------------------------------
__device__ __forceinline__ unsigned packh2(float lo, float hi) {
    unsigned r; asm("cvt.rn.f16x2.f32 %0, %1, %2;" : "=r"(r) : "f"(hi), "f"(lo)); return r;
}
__device__ __forceinline__ void mma_f16(float* c, const unsigned* a, const unsigned* b) {
    asm volatile("mma.sync.aligned.m16n8k16.row.col.f32.f16.f16.f32 "
        "{%0,%1,%2,%3},{%4,%5,%6,%7},{%8,%9},{%0,%1,%2,%3};"
        : "+f"(c[0]), "+f"(c[1]), "+f"(c[2]), "+f"(c[3])
        : "r"(a[0]), "r"(a[1]), "r"(a[2]), "r"(a[3]), "r"(b[0]), "r"(b[1]));
}
__device__ __forceinline__ void cp16(void* dst, const void* src) {
    unsigned d = (unsigned)__cvta_generic_to_shared(dst);
    asm volatile("cp.async.ca.shared.global [%0], [%1], 16;\n" :: "r"(d), "l"(src));
}
#define LDMX4(r0, r1, r2, r3, addr) \
    asm volatile("ldmatrix.sync.aligned.m8n8.x4.shared.b16 {%0,%1,%2,%3}, [%4];" \
        : "=r"(r0), "=r"(r1), "=r"(r2), "=r"(r3) : "r"(addr))
__device__ __forceinline__ uint32_t s2u(const void* p) {
    return (uint32_t)__cvta_generic_to_shared(p);
}

// ---------------------------------------------------------------------------
// Conversions
// ---------------------------------------------------------------------------
__global__ __launch_bounds__(256) void cvt_x(const float* __restrict__ q,
                                             const float* __restrict__ k,
                                             const float* __restrict__ v)
{
    const int z = blockIdx.z;
    const float* src = (z == 0) ? q : (z == 1) ? k : v;
    __half* dst = g_xh + (size_t)z * 8192 * 1024;
    size_t i = ((size_t)blockIdx.x * 256 + threadIdx.x) << 2;
    float4 val = *(const float4*)&src[i];
    *(uint2*)&dst[i] = make_uint2(packh2(val.x, val.y), packh2(val.z, val.w));
}

__global__ __launch_bounds__(256) void cvt_w(const float* __restrict__ Wq,
                                             const float* __restrict__ Wk,
                                             const float* __restrict__ Wv)
{
    __shared__ float T[64][65];
    const int z = blockIdx.z;
    const float* W = (z == 0) ? Wq : (z == 1) ? Wk : Wv;
    __half* out = (z == 0) ? g_whq : (z == 1) ? g_whk : g_whv;
    const int h = blockIdx.y, k0 = blockIdx.x << 6;
    const int tid = threadIdx.x;
    #pragma unroll
    for (int i = 0; i < 4; i++) {
        int idx = tid + (i << 8);
        int kk = idx >> 4, j = (idx & 15) << 2;
        float4 v = *(const float4*)&W[(h << 16) + ((k0 + kk) << 6) + j];
        T[kk][j] = v.x; T[kk][j + 1] = v.y; T[kk][j + 2] = v.z; T[kk][j + 3] = v.w;
    }
    __syncthreads();
    #pragma unroll
    for (int i = 0; i < 4; i++) {
        int idx = tid + (i << 8);
        int dk = idx >> 4, kk = (idx & 15) << 2;
        uint2 u = make_uint2(packh2(T[kk][dk], T[kk + 1][dk]),
                             packh2(T[kk + 2][dk], T[kk + 3][dk]));
        *(uint2*)&out[(size_t)((h << 6) + dk) * 1024 + k0 + kk] = u;
    }
}

__global__ __launch_bounds__(256) void cvt_wo(const float* __restrict__ Wo)
{
    size_t i = ((size_t)blockIdx.x * 256 + threadIdx.x) << 2;
    float4 val = *(const float4*)&Wo[i];
    *(uint2*)&g_woh[i] = make_uint2(packh2(val.x, val.y), packh2(val.z, val.w));
}

// ---------------------------------------------------------------------------
// Generic fp16 GEMM body: C[128 x 128] tile, A[m][k], B[n][k], K=1024, BK=64,
// cp.async double-buffered (validated R8 config), ldmatrix fragment loads.
// 8 warps, warp tile 64x32.
// ---------------------------------------------------------------------------
#define PSTRIDE 72   // halves per smem row (64 + 8 pad); rows 144B apart

struct GemmAcc { float a[4][4][4]; };

__device__ __forceinline__ void hgemm_core(const __half* __restrict__ Ap,
                                           const __half* __restrict__ Bp,
                                           __half* sm, GemmAcc& g,
                                           int row0, int col0)
{
    const int tid = threadIdx.x, lane = tid & 31, warp = tid >> 5;
    const int wm = warp >> 2, wn = warp & 3;
    const int STG = 2 * 128 * PSTRIDE;   // halves per stage (A + B)

    #pragma unroll
    for (int i = 0; i < 4; i++)
        #pragma unroll
        for (int j = 0; j < 4; j++)
            #pragma unroll
            for (int k = 0; k < 4; k++) g.a[i][j][k] = 0.f;

    // per-thread ldmatrix address components (bytes)
    const uint32_t arow_off = (uint32_t)(((lane & 15) * PSTRIDE + ((lane >> 4) << 3)) << 1);
    const uint32_t brow_off = (uint32_t)(((((lane & 16) >> 1) + (lane & 7)) * PSTRIDE + (lane & 8)) << 1);

    auto load_stage = [&](int st, int k0) {
        __half* A = sm + st * STG;
        __half* B = A + 128 * PSTRIDE;
        #pragma unroll
        for (int i = 0; i < 4; i++) {
            int idx = tid + (i << 8);
            int r = idx >> 3, w = (idx & 7) << 3;
            cp16(A + r * PSTRIDE + w, Ap + (size_t)(row0 + r) * 1024 + k0 + w);
        }
        #pragma unroll
        for (int i = 0; i < 4; i++) {
            int idx = tid + (i << 8);
            int n = idx >> 3, w = (idx & 7) << 3;
            cp16(B + n * PSTRIDE + w, Bp + (size_t)(col0 + n) * 1024 + k0 + w);
        }
        asm volatile("cp.async.commit_group;\n");
    };

    load_stage(0, 0);
    for (int it = 0; it < 16; it++) {
        const int st = it & 1;
        if (it + 1 < 16) {
            load_stage(st ^ 1, (it + 1) << 6);
            asm volatile("cp.async.wait_group 1;\n");
        } else {
            asm volatile("cp.async.wait_group 0;\n");
        }
        __syncthreads();
        const uint32_t Au = s2u(sm + st * STG);
        const uint32_t Bu = Au + (uint32_t)(128 * PSTRIDE * 2);
        #pragma unroll
        for (int ks = 0; ks < 4; ks++) {
            const int kb0 = ks << 4;
            unsigned a[4][4], bf[4][2];
            #pragma unroll
            for (int fm = 0; fm < 4; fm++) {
                uint32_t addr = Au + arow_off +
                    (uint32_t)(((((wm << 6) + (fm << 4)) * PSTRIDE + kb0)) << 1);
                LDMX4(a[fm][0], a[fm][1], a[fm][2], a[fm][3], addr);
            }
            #pragma unroll
            for (int p = 0; p < 2; p++) {
                uint32_t addr = Bu + brow_off +
                    (uint32_t)(((((wn << 5) + (p << 4)) * PSTRIDE + kb0)) << 1);
                LDMX4(bf[2 * p][0], bf[2 * p][1], bf[2 * p + 1][0], bf[2 * p + 1][1], addr);
            }
            #pragma unroll
            for (int fm = 0; fm < 4; fm++)
                #pragma unroll
                for (int fn = 0; fn < 4; fn++)
                    mma_f16(g.a[fm][fn], a[fm], bf[fn]);
        }
        __syncthreads();
    }
}

#define PROJ_SMEM (2 * 2 * 128 * PSTRIDE * 2)   // bytes: 2 stages x (A+B)

// Projections: q/k/v = Xh @ Wh^T + bias, output fp16.
// For zc==0 (q) the whole result (incl. bias) is scaled by log2(e)/8 so the
// scores kernel can use bare exp2f.
__global__ __launch_bounds__(256, 2) void proj_hgemm(
    const float* __restrict__ bq, const float* __restrict__ bk, const float* __restrict__ bv)
{
    extern __shared__ __align__(16) __half psm[];
    const int zc = blockIdx.z;
    const __half* X  = g_xh + (size_t)zc * 8192 * 1024;
    const __half* Wh = (zc == 0) ? g_whq : (zc == 1) ? g_whk : g_whv;
    const float* bias = (zc == 0) ? bq : (zc == 1) ? bk : bv;
    __half* out = (zc == 0) ? g_qh : (zc == 1) ? g_kh : g_vh;
    const float sc = (zc == 0) ? QSCALE : 1.0f;

    const int row0 = blockIdx.y << 7, col0 = blockIdx.x << 7;
    GemmAcc g;
    hgemm_core(X, Wh, psm, g, row0, col0);

    const int lane = threadIdx.x & 31, warp = threadIdx.x >> 5;
    const int wm = warp >> 2, wn = warp & 3;
    const int rb = lane >> 2, c2 = (lane & 3) << 1;
    #pragma unroll
    for (int fn = 0; fn < 4; fn++) {
        int c = col0 + (wn << 5) + (fn << 3) + c2;
        float b0 = bias[c], b1 = bias[c + 1];
        #pragma unroll
        for (int fm = 0; fm < 4; fm++) {
            int r = row0 + (wm << 6) + (fm << 4) + rb;
            *(unsigned*)&out[(size_t)r * 1024 + c] =
                packh2((g.a[fm][fn][0] + b0) * sc, (g.a[fm][fn][1] + b1) * sc);
            *(unsigned*)&out[(size_t)(r + 8) * 1024 + c] =
                packh2((g.a[fm][fn][2] + b0) * sc, (g.a[fm][fn][3] + b1) * sc);
        }
    }
}

// Output projection: out = ctx @ Wo^T + bo, fp32 output.
__global__ __launch_bounds__(256, 2) void out_hgemm(const float* __restrict__ bo,
                                                    float* __restrict__ out)
{
    extern __shared__ __align__(16) __half psm[];
    const int row0 = blockIdx.y << 7, col0 = blockIdx.x << 7;
    GemmAcc g;
    hgemm_core(g_ctxh, g_woh, psm, g, row0, col0);

    const int lane = threadIdx.x & 31, warp = threadIdx.x >> 5;
    const int wm = warp >> 2, wn = warp & 3;
    const int rb = lane >> 2, c2 = (lane & 3) << 1;
    #pragma unroll
    for (int fn = 0; fn < 4; fn++) {
        int c = col0 + (wn << 5) + (fn << 3) + c2;
        float b0 = bo[c], b1 = bo[c + 1];
        #pragma unroll
        for (int fm = 0; fm < 4; fm++) {
            int r = row0 + (wm << 6) + (fm << 4) + rb;
            *(float2*)&out[(size_t)r * 1024 + c] =
                make_float2(g.a[fm][fn][0] + b0, g.a[fm][fn][1] + b1);
            *(float2*)&out[(size_t)(r + 8) * 1024 + c] =
                make_float2(g.a[fm][fn][2] + b0, g.a[fm][fn][3] + b1);
        }
    }
}

// ---------------------------------------------------------------------------
// Scores pass, PERSISTENT-Q version: one block per (qtile, z).
// Q tile (128 x 64) loaded once; 16 K-tiles streamed via double-buffered
// cp.async (prefetch overlaps the exp/store epilogue of the previous tile).
// E = exp2(q'.k) -> fp16 to g_eh; per-(qtile,s) column partials -> g_part.
// smem: Q 18KB + 2xK 36.9KB + Estage 34.8KB + red 8KB = 96KB -> 2 CTAs/SM.
// ---------------------------------------------------------------------------
#define SSTRIDE 72
__global__ __launch_bounds__(256) void scores_hmma()
{
    extern __shared__ __align__(16) __half ssm[];
    __half* Qs = ssm;                        // [128][72]
    __half* Kbuf0 = ssm + 9216;              // [128][72]
    __half* Kbuf1 = ssm + 18432;             // [128][72]
    __half* Estage = ssm + 27648;            // [128][136]
    float*  red = (float*)(ssm + 45056);     // [16][128]

    const int tid = threadIdx.x, lane = tid & 31, warp = tid >> 5;
    const int wm = warp >> 2, wn = warp & 3;
    const int z = blockIdx.y, b = z >> 4, h = z & 15;
    const int q0 = blockIdx.x << 7;
    const __half* qh = g_qh + (size_t)b * 2048 * 1024 + h * 64;
    const __half* kh = g_kh + (size_t)b * 2048 * 1024 + h * 64;
    __half* ez = g_eh + (size_t)z * 2048 * 2048;

    // group 0: Q tile + K tile 0
    #pragma unroll
    for (int i = 0; i < 4; i++) {
        int idx = tid + (i << 8);
        int r = idx >> 3, w = (idx & 7) << 3;
        cp16(Qs + r * SSTRIDE + w, qh + (size_t)(q0 + r) * 1024 + w);
        cp16(Kbuf0 + r * SSTRIDE + w, kh + (size_t)r * 1024 + w);
    }
    asm volatile("cp.async.commit_group;\n");
    // group 1: K tile 1
    #pragma unroll
    for (int i = 0; i < 4; i++) {
        int idx = tid + (i << 8);
        int r = idx >> 3, w = (idx & 7) << 3;
        cp16(Kbuf1 + r * SSTRIDE + w, kh + (size_t)(128 + r) * 1024 + w);
    }
    asm volatile("cp.async.commit_group;\n");

    const uint32_t Qu = s2u(Qs);
    const uint32_t arow_off = (uint32_t)(((lane & 15) * SSTRIDE + ((lane >> 4) << 3)) << 1);
    const uint32_t brow_off = (uint32_t)(((((lane & 16) >> 1) + (lane & 7)) * SSTRIDE + (lane & 8)) << 1);
    const int rb = lane >> 2, c2 = (lane & 3) << 1;
    const int rg = (wm << 3) + rb;

    for (int it = 0; it < 16; it++) {
        __half* Ks = (it & 1) ? Kbuf1 : Kbuf0;
        const int s0 = it << 7;
        if (it < 15) asm volatile("cp.async.wait_group 1;\n");
        else         asm volatile("cp.async.wait_group 0;\n");
        __syncthreads();

        float acc[4][4][4];
        #pragma unroll
        for (int i = 0; i < 4; i++)
            #pragma unroll
            for (int j = 0; j < 4; j++)
                #pragma unroll
                for (int k = 0; k < 4; k++) acc[i][j][k] = 0.f;

        const uint32_t Ku = s2u(Ks);
        #pragma unroll
        for (int ks = 0; ks < 4; ks++) {
            const int kb0 = ks << 4;
            unsigned a[4][4], bf[4][2];
            #pragma unroll
            for (int fm = 0; fm < 4; fm++) {
                uint32_t addr = Qu + arow_off +
                    (uint32_t)((((wm << 6) + (fm << 4)) * SSTRIDE + kb0) << 1);
                LDMX4(a[fm][0], a[fm][1], a[fm][2], a[fm][3], addr);
            }
            #pragma unroll
            for (int p = 0; p < 2; p++) {
                uint32_t addr = Ku + brow_off +
                    (uint32_t)((((wn << 5) + (p << 4)) * SSTRIDE + kb0) << 1);
                LDMX4(bf[2 * p][0], bf[2 * p][1], bf[2 * p + 1][0], bf[2 * p + 1][1], addr);
            }
            #pragma unroll
            for (int fm = 0; fm < 4; fm++)
                #pragma unroll
                for (int fn = 0; fn < 4; fn++)
                    mma_f16(acc[fm][fn], a[fm], bf[fn]);
        }
        __syncthreads();   // all warps done reading Ks[st]

        // prefetch K tile it+2 into the buffer just consumed; overlaps epilogue
        if (it + 2 < 16) {
            #pragma unroll
            for (int i = 0; i < 4; i++) {
                int idx = tid + (i << 8);
                int r = idx >> 3, w = (idx & 7) << 3;
                cp16(Ks + r * SSTRIDE + w, kh + (size_t)(s0 + 256 + r) * 1024 + w);
            }
            asm volatile("cp.async.commit_group;\n");
        }

        // epilogue: exp2, stage E, column partials
        float colacc[8];
        #pragma unroll
        for (int i = 0; i < 8; i++) colacc[i] = 0.f;
        #pragma unroll
        for (int fm = 0; fm < 4; fm++) {
            int m0 = (wm << 6) + (fm << 4) + rb;
            #pragma unroll
            for (int fn = 0; fn < 4; fn++) {
                int n = (wn << 5) + (fn << 3) + c2;
                float e0 = exp2f(acc[fm][fn][0]);
                float e1 = exp2f(acc[fm][fn][1]);
                float e2 = exp2f(acc[fm][fn][2]);
                float e3 = exp2f(acc[fm][fn][3]);
                colacc[2 * fn]     += e0 + e2;
                colacc[2 * fn + 1] += e1 + e3;
                *(unsigned*)&Estage[m0 * 136 + n]       = packh2(e0, e1);
                *(unsigned*)&Estage[(m0 + 8) * 136 + n] = packh2(e2, e3);
            }
        }
        __syncthreads();

        #pragma unroll
        for (int i = 0; i < 8; i++) {
            int idx = tid + (i << 8);
            int q = idx >> 4, w = idx & 15;
            *(uint4*)(ez + (size_t)(q0 + q) * 2048 + s0 + (w << 3)) =
                *(uint4*)&Estage[q * 136 + (w << 3)];
        }

        #pragma unroll
        for (int fn = 0; fn < 4; fn++) {
            int cc = (wn << 5) + (fn << 3) + c2;
            red[rg * 128 + cc]     = colacc[2 * fn];
            red[rg * 128 + cc + 1] = colacc[2 * fn + 1];
        }
        __syncthreads();
        if (tid < 128) {
            float s = 0.f;
            #pragma unroll
            for (int t = 0; t < 16; t++) s += red[t * 128 + tid];
            g_part[((size_t)z * 16 + blockIdx.x) * 2048 + s0 + tid] = s;
        }
    }
}

// ---------------------------------------------------------------------------
// V' = V * rz -> fp16 transposed: g_vt[z][dk][s].
// rz computed inline from the 16 per-qtile partials (recip kernel fused).
// ---------------------------------------------------------------------------
__global__ __launch_bounds__(256) void v2h_fold()
{
    __shared__ float T[64][68];
    __shared__ float rzs[64];
    const int tid = threadIdx.x;
    const int z = blockIdx.y, b = z >> 4, h = z & 15;
    const int s0 = blockIdx.x << 6;
    const __half* vh = g_vh + (size_t)b * 2048 * 1024 + h * 64;
    #pragma unroll
    for (int i = 0; i < 4; i++) {
        int idx = tid + (i << 8);
        int s = idx >> 4, j = (idx & 15) << 2;
        const __half* p = vh + (size_t)(s0 + s) * 1024 + j;
        T[s][j]     = __half2float(p[0]);
        T[s][j + 1] = __half2float(p[1]);
        T[s][j + 2] = __half2float(p[2]);
        T[s][j + 3] = __half2float(p[3]);
    }
    if (tid < 64) {
        float s = 0.f;
        #pragma unroll
        for (int t = 0; t < 16; t++)
            s += g_part[((size_t)z * 16 + t) * 2048 + s0 + tid];
        rzs[tid] = 1.0f / s;
    }
    __syncthreads();
    __half* outp = g_vt + (size_t)z * 64 * 2048;
    #pragma unroll
    for (int i = 0; i < 4; i++) {
        int idx = tid + (i << 8);
        int dk = idx >> 4, sj = (idx & 15) << 2;
        uint2 u;
        u.x = packh2(T[sj][dk] * rzs[sj],         T[sj + 1][dk] * rzs[sj + 1]);
        u.y = packh2(T[sj + 2][dk] * rzs[sj + 2], T[sj + 3][dk] * rzs[sj + 3]);
        *(uint2*)(outp + dk * 2048 + s0 + sj) = u;
    }
}

// ---------------------------------------------------------------------------
// ctx = Eh @ V'^T per (b,h): [2048 x 64] = [2048 x 2048] x [2048 x 64].
// Block 256q x 64dk; 8 warps, each 32q x 64dk (validated R8 config:
// B frags serve 2x the HMMA, 2 CTAs/SM). fp16 mma, fp32 accum,
// cp.async double-buffered, ldmatrix loads; fp16 out.
// ---------------------------------------------------------------------------
#define CSTRIDE 72
__global__ __launch_bounds__(256, 2) void ctx_hgemm()
{
    extern __shared__ __align__(16) __half hsm[];
    const int STG = (256 + 64) * CSTRIDE;   // halves per stage (E 256 rows + V 64 rows)

    const int tid = threadIdx.x, lane = tid & 31, warp = tid >> 5;
    const int z = blockIdx.y, b = z >> 4, h = z & 15;
    const int q0 = blockIdx.x << 8;
    const __half* ez = g_eh + (size_t)z * 2048 * 2048;
    const __half* vt = g_vt + (size_t)z * 64 * 2048;

    float acc[2][8][4];
    #pragma unroll
    for (int f = 0; f < 2; f++)
        #pragma unroll
        for (int i = 0; i < 8; i++)
            #pragma unroll
            for (int j = 0; j < 4; j++) acc[f][i][j] = 0.f;

    const uint32_t arow_off = (uint32_t)(((lane & 15) * CSTRIDE + ((lane >> 4) << 3)) << 1);
    const uint32_t brow_off = (uint32_t)(((((lane & 16) >> 1) + (lane & 7)) * CSTRIDE + (lane & 8)) << 1);

    auto load_stage = [&](int st, int s0) {
        __half* E = hsm + st * STG;
        __half* V = E + 256 * CSTRIDE;
        #pragma unroll
        for (int i = 0; i < 8; i++) {
            int idx = tid + (i << 8);
            int q = idx >> 3, w = idx & 7;
            cp16(E + q * CSTRIDE + (w << 3), ez + (size_t)(q0 + q) * 2048 + s0 + (w << 3));
        }
        #pragma unroll
        for (int i = 0; i < 2; i++) {
            int idx = tid + (i << 8);
            int dk = idx >> 3, w = idx & 7;
            cp16(V + dk * CSTRIDE + (w << 3), vt + dk * 2048 + s0 + (w << 3));
        }
        asm volatile("cp.async.commit_group;\n");
    };

    load_stage(0, 0);
    for (int it = 0; it < 32; it++) {
        const int st = it & 1;
        if (it + 1 < 32) {
            load_stage(st ^ 1, (it + 1) << 6);
            asm volatile("cp.async.wait_group 1;\n");
        } else {
            asm volatile("cp.async.wait_group 0;\n");
        }
        __syncthreads();
        const uint32_t Eu = s2u(hsm + st * STG);
        const uint32_t Vu = Eu + (uint32_t)(256 * CSTRIDE * 2);
        const int m0 = warp << 5;
        #pragma unroll
        for (int kk = 0; kk < 4; kk++) {
            const int kb0 = kk << 4;
            unsigned a[2][4];
            #pragma unroll
            for (int fm = 0; fm < 2; fm++)
                LDMX4(a[fm][0], a[fm][1], a[fm][2], a[fm][3],
                      Eu + arow_off + (uint32_t)(((m0 + (fm << 4)) * CSTRIDE + kb0) << 1));
            unsigned bf[8][2];
            #pragma unroll
            for (int p = 0; p < 4; p++) {
                LDMX4(bf[2 * p][0], bf[2 * p][1], bf[2 * p + 1][0], bf[2 * p + 1][1],
                      Vu + brow_off + (uint32_t)(((p << 4) * CSTRIDE + kb0) << 1));
            }
            #pragma unroll
            for (int fm = 0; fm < 2; fm++)
                #pragma unroll
                for (int fb = 0; fb < 8; fb++)
                    mma_f16(acc[fm][fb], a[fm], bf[fb]);
        }
        __syncthreads();
    }

    __half* outp = g_ctxh + ((size_t)b * 2048 + q0) * 1024 + h * 64;
    const int c2 = (lane & 3) << 1;
    #pragma unroll
    for (int fm = 0; fm < 2; fm++) {
        const int q = (warp << 5) + (fm << 4) + (lane >> 2);
        #pragma unroll
        for (int fb = 0; fb < 8; fb++) {
            int dk = (fb << 3) + c2;
            *(unsigned*)&outp[(size_t)q * 1024 + dk]       = packh2(acc[fm][fb][0], acc[fm][fb][1]);
            *(unsigned*)&outp[(size_t)(q + 8) * 1024 + dk] = packh2(acc[fm][fb][2], acc[fm][fb][3]);
        }
    }
}

extern "C" void kernel_launch(void* const* d_in, const int* in_sizes, int n_in,
                              void* d_out, int out_size)
{
    const float* query = (const float*)d_in[0];
    const float* key_  = (const float*)d_in[1];
    const float* value = (const float*)d_in[2];
    const float* Wq    = (const float*)d_in[3];
    const float* bq    = (const float*)d_in[4];
    const float* Wk    = (const float*)d_in[5];
    const float* bk    = (const float*)d_in[6];
    const float* Wv    = (const float*)d_in[7];
    const float* bv    = (const float*)d_in[8];
    const float* Wo    = (const float*)d_in[9];
    const float* bo    = (const float*)d_in[10];
    float* out = (float*)d_out;

    const int ctx_smem = 2 * (256 + 64) * CSTRIDE * 2;   // 92160 bytes
    const int scores_smem = 98304;                        // 96 KB
    cudaFuncSetAttribute(proj_hgemm,  cudaFuncAttributeMaxDynamicSharedMemorySize, PROJ_SMEM);
    cudaFuncSetAttribute(out_hgemm,   cudaFuncAttributeMaxDynamicSharedMemorySize, PROJ_SMEM);
    cudaFuncSetAttribute(ctx_hgemm,   cudaFuncAttributeMaxDynamicSharedMemorySize, ctx_smem);
    cudaFuncSetAttribute(scores_hmma, cudaFuncAttributeMaxDynamicSharedMemorySize, scores_smem);

    cvt_x<<<dim3(8192, 1, 3), 256>>>(query, key_, value);
    cvt_w<<<dim3(16, 16, 3), 256>>>(Wq, Wk, Wv);
    cvt_wo<<<1024, 256>>>(Wo);
    proj_hgemm<<<dim3(8, 64, 3), 256, PROJ_SMEM>>>(bq, bk, bv);
    scores_hmma<<<dim3(16, 64), 256, scores_smem>>>();
    v2h_fold<<<dim3(32, 64), 256>>>();
    ctx_hgemm<<<dim3(8, 64), 256, ctx_smem>>>();
    out_hgemm<<<dim3(8, 64), 256, PROJ_SMEM>>>(bo, out);
}